// round 2
// baseline (speedup 1.0000x reference)
#include <cuda_runtime.h>
#include <cuda_bf16.h>
#include <math.h>
#include <stdint.h>

// ---------------- problem constants ----------------
#define BT      8
#define SEQ     576
#define MTOT    (BT * SEQ)        // 4608
#define NLF     25                // layers in features
#define DIM     2048              // D
#define CTD     1024              // CT
#define NLAYER  7
#define HEADS   8
#define HDIM    128
#define ATT_SCALE 0.03125f        // CT^-0.5
#define LN_EPSF   1e-5f
#define COS_EPSF  1e-8f

// ---------------- device scratch ----------------
__device__ __nv_bfloat16 g_xn[(size_t)8 * MTOT * DIM];   // slots 0..6 LN'd layers, slot 7 = raw layer 24
__device__ __nv_bfloat16 g_wb[(size_t)8 * DIM * CTD];    // slots 0..6 w_norm, slot 7 = w_in
__device__ __nv_bfloat16 g_wo[(size_t)CTD * CTD];
__device__ float g_v[(size_t)MTOT * 8 * CTD];            // slots 0..6 vout, 7 = vin (fp32)
__device__ __nv_bfloat16 g_fuse[(size_t)MTOT * CTD];
__device__ float g_vf[(size_t)MTOT * CTD];
__device__ float g_cos[MTOT];

// ---------------- helpers ----------------
__device__ __forceinline__ float warp_sum(float v) {
#pragma unroll
    for (int o = 16; o > 0; o >>= 1) v += __shfl_xor_sync(0xffffffffu, v, o);
    return v;
}
__device__ __forceinline__ uint32_t smem_u32(const void* p) {
    return (uint32_t)__cvta_generic_to_shared(p);
}
__device__ __forceinline__ void cp16(uint32_t dst, const void* src) {
    asm volatile("cp.async.cg.shared.global [%0], [%1], 16;\n" :: "r"(dst), "l"(src));
}
__device__ __forceinline__ void ldmx4(uint32_t* r, uint32_t addr) {
    asm volatile("ldmatrix.sync.aligned.m8n8.x4.shared.b16 {%0,%1,%2,%3}, [%4];\n"
        : "=r"(r[0]), "=r"(r[1]), "=r"(r[2]), "=r"(r[3]) : "r"(addr));
}
__device__ __forceinline__ void ldmx4t(uint32_t* r, uint32_t addr) {
    asm volatile("ldmatrix.sync.aligned.m8n8.x4.trans.shared.b16 {%0,%1,%2,%3}, [%4];\n"
        : "=r"(r[0]), "=r"(r[1]), "=r"(r[2]), "=r"(r[3]) : "r"(addr));
}
__device__ __forceinline__ void mma_bf16(float* c, const uint32_t* a, const uint32_t* b) {
    asm volatile(
        "mma.sync.aligned.m16n8k16.row.col.f32.bf16.bf16.f32 "
        "{%0,%1,%2,%3}, {%4,%5,%6,%7}, {%8,%9}, {%0,%1,%2,%3};\n"
        : "+f"(c[0]), "+f"(c[1]), "+f"(c[2]), "+f"(c[3])
        : "r"(a[0]), "r"(a[1]), "r"(a[2]), "r"(a[3]), "r"(b[0]), "r"(b[1]));
}
__device__ __forceinline__ uint2 f4_to_bf4(float4 v) {
    __nv_bfloat162 lo = __floats2bfloat162_rn(v.x, v.y);
    __nv_bfloat162 hi = __floats2bfloat162_rn(v.z, v.w);
    uint2 r;
    r.x = *reinterpret_cast<uint32_t*>(&lo);
    r.y = *reinterpret_cast<uint32_t*>(&hi);
    return r;
}

// ---------------- 0) convert weights to bf16 ----------------
#define WN4 ((size_t)7 * DIM * CTD / 4)
#define WI4 ((size_t)DIM * CTD / 4)
#define WO4 ((size_t)CTD * CTD / 4)
__global__ void __launch_bounds__(256) convert_weights(
    const float* __restrict__ wn, const float* __restrict__ wi,
    const float* __restrict__ wo)
{
    size_t i = (size_t)blockIdx.x * 256 + threadIdx.x;
    if (i < WN4) {
        reinterpret_cast<uint2*>(g_wb)[i] =
            f4_to_bf4(reinterpret_cast<const float4*>(wn)[i]);
    } else if (i < WN4 + WI4) {
        size_t j = i - WN4;
        reinterpret_cast<uint2*>(g_wb + (size_t)7 * DIM * CTD)[j] =
            f4_to_bf4(reinterpret_cast<const float4*>(wi)[j]);
    } else if (i < WN4 + WI4 + WO4) {
        size_t j = i - WN4 - WI4;
        reinterpret_cast<uint2*>(g_wo)[j] =
            f4_to_bf4(reinterpret_cast<const float4*>(wo)[j]);
    }
}

// ---------------- 1) gather + layernorm -> bf16 ----------------
// grid MTOT*8, 256 threads. slot l<7: LN of layer 24-4l. slot 7: raw layer 24.
__global__ void __launch_bounds__(256) ln_kernel(
    const float* __restrict__ features,
    const float* __restrict__ ln_scale,
    const float* __restrict__ ln_bias)
{
    int l = blockIdx.x & 7;
    int m = blockIdx.x >> 3;
    int layer = (l < 7) ? (24 - 4 * l) : 24;
    const float4* x = reinterpret_cast<const float4*>(
        features + ((size_t)m * NLF + layer) * DIM);
    int t = threadIdx.x;

    float4 a = x[t];
    float4 b = x[t + 256];
    uint2* o = reinterpret_cast<uint2*>(g_xn + ((size_t)l * MTOT + m) * DIM);

    if (l == 7) {
        o[t] = f4_to_bf4(a);
        o[t + 256] = f4_to_bf4(b);
        return;
    }

    float s  = a.x + a.y + a.z + a.w + b.x + b.y + b.z + b.w;
    float ss = a.x*a.x + a.y*a.y + a.z*a.z + a.w*a.w
             + b.x*b.x + b.y*b.y + b.z*b.z + b.w*b.w;

    __shared__ float shs[8], shss[8];
    float ws  = warp_sum(s);
    float wss = warp_sum(ss);
    int w = t >> 5, lane = t & 31;
    if (lane == 0) { shs[w] = ws; shss[w] = wss; }
    __syncthreads();
    float tot = 0.f, tot2 = 0.f;
#pragma unroll
    for (int i = 0; i < 8; i++) { tot += shs[i]; tot2 += shss[i]; }

    float mu  = tot * (1.0f / DIM);
    float var = tot2 * (1.0f / DIM) - mu * mu;
    float rs  = rsqrtf(var + LN_EPSF);

    const float4* sc = reinterpret_cast<const float4*>(ln_scale + (size_t)l * DIM);
    const float4* bi = reinterpret_cast<const float4*>(ln_bias  + (size_t)l * DIM);
    float4 s0 = sc[t],       b0 = bi[t];
    float4 s1 = sc[t + 256], b1 = bi[t + 256];
    float4 o0, o1;
    o0.x = (a.x - mu) * rs * s0.x + b0.x;
    o0.y = (a.y - mu) * rs * s0.y + b0.y;
    o0.z = (a.z - mu) * rs * s0.z + b0.z;
    o0.w = (a.w - mu) * rs * s0.w + b0.w;
    o1.x = (b.x - mu) * rs * s1.x + b1.x;
    o1.y = (b.y - mu) * rs * s1.y + b1.y;
    o1.z = (b.z - mu) * rs * s1.z + b1.z;
    o1.w = (b.w - mu) * rs * s1.w + b1.w;
    o[t] = f4_to_bf4(o0);
    o[t + 256] = f4_to_bf4(o1);
}

// ---------------- 2) bf16 tensor-core GEMM ----------------
// CTA tile 128x128x32, 8 warps (4x2), warp tile 32x64, mma m16n8k16.
// MODE 0: g_xn[z] @ g_wb[z] -> g_v slot z (+ b_in if z==7).  K = DIM.
// MODE 1: g_fuse @ g_wo + vin + b_out -> g_vf.              K = CTD.
#define AST 40      // A smem row stride in halves (conflict-free ldmatrix)
#define BST 136     // B smem row stride in halves
#define ABYTES (128 * AST * 2)
#define BBYTES (32 * BST * 2)
#define BUFBYTES (ABYTES + BBYTES)

template<int NKT, int MODE>
__global__ void __launch_bounds__(256, 2) mma_gemm(
    const __nv_bfloat16* __restrict__ Ab,
    const __nv_bfloat16* __restrict__ Bb,
    const float* __restrict__ bias)
{
    __shared__ __align__(16) char smem[2 * BUFBYTES];
    int tid = threadIdx.x;
    int m0 = blockIdx.y * 128, n0 = blockIdx.x * 128;
    int z = (MODE == 0) ? blockIdx.z : 0;
    const __nv_bfloat16* A = (MODE == 0) ? Ab + (size_t)z * MTOT * DIM : Ab;
    const __nv_bfloat16* B = (MODE == 0) ? Bb + (size_t)z * DIM * CTD : Bb;
    const int lda = (MODE == 0) ? DIM : CTD;

    // loader layout
    int arow = tid >> 1,  acol = (tid & 1) * 16;   // A: 128 rows x 32 halves
    int brow = tid >> 3,  bcol = (tid & 7) * 16;   // B: 32 rows x 128 halves
    const __nv_bfloat16* ag = A + (size_t)(m0 + arow) * lda + acol;
    const __nv_bfloat16* bg = B + (size_t)brow * CTD + n0 + bcol;
    uint32_t sa = smem_u32(smem);
    uint32_t adst = sa + arow * (AST * 2) + acol * 2;
    uint32_t bdst = sa + ABYTES + brow * (BST * 2) + bcol * 2;

    int lane = tid & 31, wid = tid >> 5;
    int wm = wid >> 1, wn = wid & 1;
    int lr = lane & 15, lc = (lane >> 4) * 8;

    float acc[2][8][4];
#pragma unroll
    for (int i = 0; i < 2; i++)
#pragma unroll
        for (int j = 0; j < 8; j++)
#pragma unroll
            for (int k = 0; k < 4; k++) acc[i][j][k] = 0.f;

    // prefetch tile 0 into buf 0
    {
        cp16(adst, ag);          cp16(adst + 16, ag + 8);
        cp16(bdst, bg);          cp16(bdst + 16, bg + 8);
    }
    asm volatile("cp.async.commit_group;\n");

    for (int kt = 0; kt < NKT; kt++) {
        if (kt + 1 < NKT) {
            int nb = (kt + 1) & 1;
            const __nv_bfloat16* a = ag + (kt + 1) * 32;
            const __nv_bfloat16* b = bg + (size_t)(kt + 1) * 32 * CTD;
            uint32_t ad = adst + nb * BUFBYTES;
            uint32_t bd = bdst + nb * BUFBYTES;
            cp16(ad, a);         cp16(ad + 16, a + 8);
            cp16(bd, b);         cp16(bd + 16, b + 8);
        }
        asm volatile("cp.async.commit_group;\n");
        asm volatile("cp.async.wait_group 1;\n");
        __syncthreads();

        int buf = kt & 1;
        uint32_t abase = sa + buf * BUFBYTES;
        uint32_t bbase = abase + ABYTES;
#pragma unroll
        for (int ks = 0; ks < 2; ks++) {
            uint32_t af[2][4];
            ldmx4(af[0], abase + ((wm * 32 +      lr) * AST + ks * 16 + lc) * 2);
            ldmx4(af[1], abase + ((wm * 32 + 16 + lr) * AST + ks * 16 + lc) * 2);
#pragma unroll
            for (int j = 0; j < 4; j++) {
                uint32_t bfr[4];
                ldmx4t(bfr, bbase + ((ks * 16 + lr) * BST + wn * 64 + j * 16 + lc) * 2);
                mma_bf16(acc[0][2 * j],     af[0], bfr);
                mma_bf16(acc[0][2 * j + 1], af[0], bfr + 2);
                mma_bf16(acc[1][2 * j],     af[1], bfr);
                mma_bf16(acc[1][2 * j + 1], af[1], bfr + 2);
            }
        }
        __syncthreads();
    }

    // epilogue
    int g = lane >> 2, tg = lane & 3;
#pragma unroll
    for (int i = 0; i < 2; i++) {
#pragma unroll
        for (int j = 0; j < 8; j++) {
            int m = m0 + wm * 32 + i * 16 + g;
            int n = n0 + wn * 64 + j * 8 + tg * 2;
            float2 lo = make_float2(acc[i][j][0], acc[i][j][1]);   // row m
            float2 hi = make_float2(acc[i][j][2], acc[i][j][3]);   // row m+8
            if (MODE == 0) {
                if (z == 7) {
                    float2 bb = *reinterpret_cast<const float2*>(bias + n);
                    lo.x += bb.x; lo.y += bb.y;
                    hi.x += bb.x; hi.y += bb.y;
                }
                float* c = g_v + (size_t)m * (8 * CTD) + (size_t)z * CTD + n;
                *reinterpret_cast<float2*>(c) = lo;
                *reinterpret_cast<float2*>(c + (size_t)8 * 8 * CTD) = hi;
            } else {
                float2 bb = *reinterpret_cast<const float2*>(bias + n);
                const float2 v0 = *reinterpret_cast<const float2*>(
                    g_v + (size_t)m * (8 * CTD) + 7 * CTD + n);
                const float2 v1 = *reinterpret_cast<const float2*>(
                    g_v + (size_t)(m + 8) * (8 * CTD) + 7 * CTD + n);
                lo.x += v0.x + bb.x; lo.y += v0.y + bb.y;
                hi.x += v1.x + bb.x; hi.y += v1.y + bb.y;
                *reinterpret_cast<float2*>(g_vf + (size_t)m * CTD + n) = lo;
                *reinterpret_cast<float2*>(g_vf + (size_t)(m + 8) * CTD + n) = hi;
            }
        }
    }
}

// ---------------- 3) attention fuse (fp32 in, bf16 out) ----------------
__global__ void __launch_bounds__(128) attn_kernel()
{
    int m = blockIdx.x, t = threadIdx.x;
    const float* vrow = g_v + (size_t)m * 8 * CTD;
    __shared__ float shp[6][4];
    __shared__ float slog[6];
    int w = t >> 5, lane = t & 31;

    for (int h = 0; h < HEADS; h++) {
        float q = vrow[h * HDIM + t] * ATT_SCALE;
        float kv[6];
#pragma unroll
        for (int l = 0; l < 6; l++)
            kv[l] = vrow[(size_t)(l + 1) * CTD + h * HDIM + t];
#pragma unroll
        for (int l = 0; l < 6; l++) {
            float p = warp_sum(q * kv[l]);
            if (lane == 0) shp[l][w] = p;
        }
        __syncthreads();
        if (t < 6) slog[t] = shp[t][0] + shp[t][1] + shp[t][2] + shp[t][3];
        __syncthreads();
        float mx = -1e30f;
#pragma unroll
        for (int l = 0; l < 6; l++) mx = fmaxf(mx, slog[l]);
        float e[6], sum = 0.f;
#pragma unroll
        for (int l = 0; l < 6; l++) { e[l] = expf(slog[l] - mx); sum += e[l]; }
        float inv = 1.0f / sum;
        float f = 0.f;
#pragma unroll
        for (int l = 0; l < 6; l++) f += (e[l] * inv) * kv[l];
        g_fuse[(size_t)m * CTD + h * HDIM + t] = __float2bfloat16_rn(f);
        __syncthreads();
    }
}

// ---------------- 5) per-row cosine ----------------
__global__ void __launch_bounds__(256) cos_kernel(const float* __restrict__ teacher)
{
    int m = blockIdx.x, t = threadIdx.x;
    const float4* a = reinterpret_cast<const float4*>(g_vf + (size_t)m * CTD);
    const float4* b = reinterpret_cast<const float4*>(teacher + (size_t)m * CTD);
    float4 x = a[t], y = b[t];
    float dot = x.x*y.x + x.y*y.y + x.z*y.z + x.w*y.w;
    float n1  = x.x*x.x + x.y*x.y + x.z*x.z + x.w*x.w;
    float n2  = y.x*y.x + y.y*y.y + y.z*y.z + y.w*y.w;

    __shared__ float sd[8], s1[8], s2[8];
    float wd = warp_sum(dot), w1 = warp_sum(n1), w2 = warp_sum(n2);
    int w = t >> 5, lane = t & 31;
    if (lane == 0) { sd[w] = wd; s1[w] = w1; s2[w] = w2; }
    __syncthreads();
    if (t == 0) {
        float td = 0.f, t1 = 0.f, t2 = 0.f;
#pragma unroll
        for (int i = 0; i < 8; i++) { td += sd[i]; t1 += s1[i]; t2 += s2[i]; }
        float na = fmaxf(sqrtf(t1), COS_EPSF);
        float nb = fmaxf(sqrtf(t2), COS_EPSF);
        g_cos[m] = td / (na * nb);
    }
}

// ---------------- 6) final deterministic reduction ----------------
__global__ void __launch_bounds__(512) final_kernel(float* __restrict__ out)
{
    __shared__ float sh[512];
    int t = threadIdx.x;
    float s = 0.f;
    for (int i = t; i < MTOT; i += 512) s += g_cos[i];
    sh[t] = s;
    __syncthreads();
    for (int o = 256; o > 0; o >>= 1) {
        if (t < o) sh[t] += sh[t + o];
        __syncthreads();
    }
    if (t == 0) out[0] = 1.0f - sh[0] / (float)MTOT;
}

// ---------------- launch ----------------
extern "C" void kernel_launch(void* const* d_in, const int* in_sizes, int n_in,
                              void* d_out, int out_size)
{
    const float* features = (const float*)d_in[0];
    const float* teacher  = (const float*)d_in[1];
    const float* ln_scale = (const float*)d_in[2];
    const float* ln_bias  = (const float*)d_in[3];
    const float* w_norm   = (const float*)d_in[4];
    const float* w_in     = (const float*)d_in[5];
    const float* b_in     = (const float*)d_in[6];
    const float* w_out    = (const float*)d_in[7];
    const float* b_out    = (const float*)d_in[8];
    float* out = (float*)d_out;

    size_t total4 = WN4 + WI4 + WO4;
    convert_weights<<<(unsigned)((total4 + 255) / 256), 256>>>(w_norm, w_in, w_out);
    ln_kernel<<<MTOT * 8, 256>>>(features, ln_scale, ln_bias);
    mma_gemm<64, 0><<<dim3(CTD / 128, MTOT / 128, 8), 256>>>(g_xn, g_wb, b_in);
    attn_kernel<<<MTOT, 128>>>();
    mma_gemm<32, 1><<<dim3(CTD / 128, MTOT / 128, 1), 256>>>(g_fuse, g_wo, b_out);
    cos_kernel<<<MTOT, 256>>>(teacher);
    final_kernel<<<1, 512>>>(out);
}

// round 4
// speedup vs baseline: 9.0239x; 9.0239x over previous
#include <cuda_runtime.h>
#include <math.h>
#include <stdint.h>

// ---------------- problem constants ----------------
#define BT      8
#define SEQ     576
#define MTOT    (BT * SEQ)        // 4608
#define NLF     25
#define DIM     2048              // D
#define CTD     1024              // CT
#define HEADS   8
#define HDIM    128
#define ATT_SCALE 0.03125f
#define LN_EPSF   1e-5f
#define COS_EPSF  1e-8f

typedef unsigned long long ull;

// ---------------- device scratch ----------------
__device__ float g_xn[(size_t)7 * MTOT * DIM];   // layernormed slices, per-layer contiguous
__device__ float g_v[(size_t)MTOT * 8 * CTD];    // per row: slots 0..6 vout, slot 7 vin
__device__ float g_fuse[(size_t)MTOT * CTD];
__device__ float g_vf[(size_t)MTOT * CTD];
__device__ float g_cos[MTOT];

// ---------------- helpers ----------------
__device__ __forceinline__ float warp_sum(float v) {
#pragma unroll
    for (int o = 16; o > 0; o >>= 1) v += __shfl_xor_sync(0xffffffffu, v, o);
    return v;
}
__device__ __forceinline__ void cp16(void* dst, const void* src) {
    uint32_t d = (uint32_t)__cvta_generic_to_shared(dst);
    asm volatile("cp.async.cg.shared.global [%0], [%1], 16;\n" :: "r"(d), "l"(src));
}
__device__ __forceinline__ void ffma2(ull& acc, ull a, ull b) {
    asm volatile("fma.rn.f32x2 %0, %1, %2, %0;\n" : "+l"(acc) : "l"(a), "l"(b));
}

// ---------------- 1) gather + layernorm (fp32 out) ----------------
__global__ void __launch_bounds__(256) ln_kernel(
    const float* __restrict__ features,
    const float* __restrict__ ln_scale,
    const float* __restrict__ ln_bias)
{
    int l = blockIdx.x % 7;
    int m = blockIdx.x / 7;
    int layer = 24 - 4 * l;
    const float4* x = reinterpret_cast<const float4*>(
        features + ((size_t)m * NLF + layer) * DIM);
    int t = threadIdx.x;

    float4 a = x[t];
    float4 b = x[t + 256];
    float s  = a.x + a.y + a.z + a.w + b.x + b.y + b.z + b.w;
    float ss = a.x*a.x + a.y*a.y + a.z*a.z + a.w*a.w
             + b.x*b.x + b.y*b.y + b.z*b.z + b.w*b.w;

    __shared__ float shs[8], shss[8];
    float ws  = warp_sum(s);
    float wss = warp_sum(ss);
    int w = t >> 5, lane = t & 31;
    if (lane == 0) { shs[w] = ws; shss[w] = wss; }
    __syncthreads();
    float tot = 0.f, tot2 = 0.f;
#pragma unroll
    for (int i = 0; i < 8; i++) { tot += shs[i]; tot2 += shss[i]; }

    float mu  = tot * (1.0f / DIM);
    float var = tot2 * (1.0f / DIM) - mu * mu;
    float rs  = rsqrtf(var + LN_EPSF);

    const float4* sc = reinterpret_cast<const float4*>(ln_scale + (size_t)l * DIM);
    const float4* bi = reinterpret_cast<const float4*>(ln_bias  + (size_t)l * DIM);
    float4* o = reinterpret_cast<float4*>(g_xn + ((size_t)l * MTOT + m) * DIM);

    float4 s0 = sc[t],       b0 = bi[t];
    float4 s1 = sc[t + 256], b1 = bi[t + 256];
    float4 o0, o1;
    o0.x = (a.x - mu) * rs * s0.x + b0.x;
    o0.y = (a.y - mu) * rs * s0.y + b0.y;
    o0.z = (a.z - mu) * rs * s0.z + b0.z;
    o0.w = (a.w - mu) * rs * s0.w + b0.w;
    o1.x = (b.x - mu) * rs * s1.x + b1.x;
    o1.y = (b.y - mu) * rs * s1.y + b1.y;
    o1.z = (b.z - mu) * rs * s1.z + b1.z;
    o1.w = (b.w - mu) * rs * s1.w + b1.w;
    o[t] = o0;
    o[t + 256] = o1;
}

// ---------------- 2) FFMA2 GEMM: 128x128x16, double-buffered ----------------
// MODE 0: z<7: g_xn[z] @ w_norm[z]; z==7: features[:,:,24] @ w_in + b_in -> g_v slot z
// MODE 1: g_fuse @ w_out (+ vin + b_out) -> g_vf
// B consumed in original [K, N=CTD] row-major layout.
template<int NKT, int MODE>
__global__ void __launch_bounds__(256, 2) gemm_f32x2(
    const float* __restrict__ features,
    const float* __restrict__ w_norm,
    const float* __restrict__ w_in,
    const float* __restrict__ bias)     // b_in (MODE0) / b_out (MODE1)
{
    __shared__ float As2[2][16][256];   // A duplicated pairs: As2[k][2m]=As2[k][2m+1]=A[m][k]
    __shared__ float Bs[2][16][128];

    int tid = threadIdx.x;
    int m0 = blockIdx.y * 128, n0 = blockIdx.x * 128;
    int z = (MODE == 0) ? blockIdx.z : 0;

    const float* A;
    const float* B;
    size_t lda;
    if (MODE == 0) {
        if (z < 7) {
            A = g_xn + (size_t)z * MTOT * DIM;
            lda = DIM;
            B = w_norm + (size_t)z * DIM * CTD;
        } else {
            A = features + (size_t)24 * DIM;
            lda = (size_t)NLF * DIM;
            B = w_in;
        }
    } else {
        A = g_fuse; lda = CTD; B = w_in;  // w_in param carries w_out in MODE 1
    }

    // loader mapping
    int arow = tid >> 1, acol = (tid & 1) * 8;      // A: 128 rows x 16 k
    int brow = tid >> 4, bcol = (tid & 15) * 4;     // B: 16 k x 128 n
    const float* ag = A + (size_t)(m0 + arow) * lda + acol;
    const float* bg = B + (size_t)brow * CTD + n0 + bcol;

    // compute mapping
    int ty = tid >> 4, tx = tid & 15;               // rows ty*8.., col pairs jp*32+tx*2

    ull acc[8][4];
#pragma unroll
    for (int i = 0; i < 8; i++)
#pragma unroll
        for (int j = 0; j < 4; j++) acc[i][j] = 0ull;

    float4 pa0, pa1;

    // ---- prologue: tile 0 ----
    pa0 = *reinterpret_cast<const float4*>(ag);
    pa1 = *reinterpret_cast<const float4*>(ag + 4);
    cp16(&Bs[0][brow][bcol], bg);
    cp16(&Bs[0][brow][bcol + 64], bg + 64);
    asm volatile("cp.async.commit_group;\n" ::: "memory");
    {
        float va[8] = {pa0.x, pa0.y, pa0.z, pa0.w, pa1.x, pa1.y, pa1.z, pa1.w};
#pragma unroll
        for (int j = 0; j < 8; j++) {
            float2 d = make_float2(va[j], va[j]);
            *reinterpret_cast<float2*>(&As2[0][acol + j][2 * arow]) = d;
        }
    }

    for (int kt = 0; kt < NKT; kt++) {
        int buf = kt & 1;
        if (kt + 1 < NKT) {
            const float* an = ag + (kt + 1) * 16;
            const float* bn = bg + (size_t)(kt + 1) * 16 * CTD;
            pa0 = *reinterpret_cast<const float4*>(an);
            pa1 = *reinterpret_cast<const float4*>(an + 4);
            cp16(&Bs[buf ^ 1][brow][bcol], bn);
            cp16(&Bs[buf ^ 1][brow][bcol + 64], bn + 64);
            asm volatile("cp.async.commit_group;\n" ::: "memory");
            asm volatile("cp.async.wait_group 1;\n" ::: "memory");
        } else {
            asm volatile("cp.async.wait_group 0;\n" ::: "memory");
        }
        __syncthreads();

#pragma unroll
        for (int k = 0; k < 16; k++) {
            ull a[8], b[4];
#pragma unroll
            for (int i = 0; i < 8; i++)
                a[i] = *reinterpret_cast<const ull*>(&As2[buf][k][2 * (ty * 8 + i)]);
#pragma unroll
            for (int j = 0; j < 4; j++)
                b[j] = *reinterpret_cast<const ull*>(&Bs[buf][k][j * 32 + tx * 2]);
#pragma unroll
            for (int i = 0; i < 8; i++)
#pragma unroll
                for (int j = 0; j < 4; j++) ffma2(acc[i][j], a[i], b[j]);
        }

        if (kt + 1 < NKT) {
            float va[8] = {pa0.x, pa0.y, pa0.z, pa0.w, pa1.x, pa1.y, pa1.z, pa1.w};
#pragma unroll
            for (int j = 0; j < 8; j++) {
                float2 d = make_float2(va[j], va[j]);
                *reinterpret_cast<float2*>(&As2[buf ^ 1][acol + j][2 * arow]) = d;
            }
        }
    }

    // ---- epilogue ----
#pragma unroll
    for (int i = 0; i < 8; i++) {
        int m = m0 + ty * 8 + i;
#pragma unroll
        for (int j = 0; j < 4; j++) {
            int n = n0 + j * 32 + tx * 2;
            float lo = __uint_as_float((uint32_t)(acc[i][j] & 0xffffffffull));
            float hi = __uint_as_float((uint32_t)(acc[i][j] >> 32));
            if (MODE == 0) {
                if (z == 7) {
                    float2 bb = *reinterpret_cast<const float2*>(bias + n);
                    lo += bb.x; hi += bb.y;
                }
                float2 v = make_float2(lo, hi);
                *reinterpret_cast<float2*>(
                    g_v + (size_t)m * (8 * CTD) + (size_t)z * CTD + n) = v;
            } else {
                float2 bb = *reinterpret_cast<const float2*>(bias + n);
                float2 vin = *reinterpret_cast<const float2*>(
                    g_v + (size_t)m * (8 * CTD) + 7 * CTD + n);
                float2 v = make_float2(lo + bb.x + vin.x, hi + bb.y + vin.y);
                *reinterpret_cast<float2*>(g_vf + (size_t)m * CTD + n) = v;
            }
        }
    }
}

// ---------------- 3) attention fuse ----------------
__global__ void __launch_bounds__(128) attn_kernel()
{
    int m = blockIdx.x, t = threadIdx.x;
    const float* vrow = g_v + (size_t)m * 8 * CTD;
    __shared__ float shp[6][4];
    __shared__ float slog[6];
    int w = t >> 5, lane = t & 31;

    for (int h = 0; h < HEADS; h++) {
        float q = vrow[h * HDIM + t] * ATT_SCALE;
        float kv[6];
#pragma unroll
        for (int l = 0; l < 6; l++)
            kv[l] = vrow[(size_t)(l + 1) * CTD + h * HDIM + t];
#pragma unroll
        for (int l = 0; l < 6; l++) {
            float p = warp_sum(q * kv[l]);
            if (lane == 0) shp[l][w] = p;
        }
        __syncthreads();
        if (t < 6) slog[t] = shp[t][0] + shp[t][1] + shp[t][2] + shp[t][3];
        __syncthreads();
        float mx = -1e30f;
#pragma unroll
        for (int l = 0; l < 6; l++) mx = fmaxf(mx, slog[l]);
        float e[6], sum = 0.f;
#pragma unroll
        for (int l = 0; l < 6; l++) { e[l] = expf(slog[l] - mx); sum += e[l]; }
        float inv = 1.0f / sum;
        float f = 0.f;
#pragma unroll
        for (int l = 0; l < 6; l++) f += (e[l] * inv) * kv[l];
        g_fuse[(size_t)m * CTD + h * HDIM + t] = f;
        __syncthreads();
    }
}

// ---------------- 5) per-row cosine ----------------
__global__ void __launch_bounds__(256) cos_kernel(const float* __restrict__ teacher)
{
    int m = blockIdx.x, t = threadIdx.x;
    const float4* a = reinterpret_cast<const float4*>(g_vf + (size_t)m * CTD);
    const float4* b = reinterpret_cast<const float4*>(teacher + (size_t)m * CTD);
    float4 x = a[t], y = b[t];
    float dot = x.x*y.x + x.y*y.y + x.z*y.z + x.w*y.w;
    float n1  = x.x*x.x + x.y*x.y + x.z*x.z + x.w*x.w;
    float n2  = y.x*y.x + y.y*y.y + y.z*y.z + y.w*y.w;

    __shared__ float sd[8], s1[8], s2[8];
    float wd = warp_sum(dot), w1 = warp_sum(n1), w2 = warp_sum(n2);
    int w = t >> 5, lane = t & 31;
    if (lane == 0) { sd[w] = wd; s1[w] = w1; s2[w] = w2; }
    __syncthreads();
    if (t == 0) {
        float td = 0.f, t1 = 0.f, t2 = 0.f;
#pragma unroll
        for (int i = 0; i < 8; i++) { td += sd[i]; t1 += s1[i]; t2 += s2[i]; }
        float na = fmaxf(sqrtf(t1), COS_EPSF);
        float nb = fmaxf(sqrtf(t2), COS_EPSF);
        g_cos[m] = td / (na * nb);
    }
}

// ---------------- 6) final deterministic reduction ----------------
__global__ void __launch_bounds__(512) final_kernel(float* __restrict__ out)
{
    __shared__ float sh[512];
    int t = threadIdx.x;
    float s = 0.f;
    for (int i = t; i < MTOT; i += 512) s += g_cos[i];
    sh[t] = s;
    __syncthreads();
    for (int o = 256; o > 0; o >>= 1) {
        if (t < o) sh[t] += sh[t + o];
        __syncthreads();
    }
    if (t == 0) out[0] = 1.0f - sh[0] / (float)MTOT;
}

// ---------------- launch ----------------
extern "C" void kernel_launch(void* const* d_in, const int* in_sizes, int n_in,
                              void* d_out, int out_size)
{
    const float* features = (const float*)d_in[0];
    const float* teacher  = (const float*)d_in[1];
    const float* ln_scale = (const float*)d_in[2];
    const float* ln_bias  = (const float*)d_in[3];
    const float* w_norm   = (const float*)d_in[4];
    const float* w_in     = (const float*)d_in[5];
    const float* b_in     = (const float*)d_in[6];
    const float* w_out    = (const float*)d_in[7];
    const float* b_out    = (const float*)d_in[8];
    float* out = (float*)d_out;

    ln_kernel<<<MTOT * 7, 256>>>(features, ln_scale, ln_bias);
    gemm_f32x2<DIM / 16, 0><<<dim3(CTD / 128, MTOT / 128, 8), 256>>>(
        features, w_norm, w_in, b_in);
    attn_kernel<<<MTOT, 128>>>();
    gemm_f32x2<CTD / 16, 1><<<dim3(CTD / 128, MTOT / 128, 1), 256>>>(
        features, nullptr, w_out, b_out);
    cos_kernel<<<MTOT, 256>>>(teacher);
    final_kernel<<<1, 512>>>(out);
}

// round 5
// speedup vs baseline: 9.3374x; 1.0347x over previous
#include <cuda_runtime.h>
#include <math.h>
#include <stdint.h>

// ---------------- problem constants ----------------
#define BT      8
#define SEQ     576
#define MTOT    (BT * SEQ)        // 4608
#define NLF     25
#define DIM     2048              // D
#define CTD     1024              // CT
#define HEADS   8
#define HDIM    128
#define ATT_SCALE 0.03125f
#define LN_EPSF   1e-5f
#define COS_EPSF  1e-8f

typedef unsigned long long ull;

// ---------------- device scratch ----------------
__device__ float g_xn[(size_t)7 * MTOT * DIM];   // layernormed slices, per-layer contiguous
__device__ float g_v[(size_t)MTOT * 8 * CTD];    // per row: slots 0..6 vout, slot 7 vin
__device__ float g_fuse[(size_t)MTOT * CTD];
__device__ float g_vf[(size_t)MTOT * CTD];
__device__ float g_cos[MTOT];

// ---------------- helpers ----------------
__device__ __forceinline__ float warp_sum(float v) {
#pragma unroll
    for (int o = 16; o > 0; o >>= 1) v += __shfl_xor_sync(0xffffffffu, v, o);
    return v;
}
__device__ __forceinline__ void cp16(void* dst, const void* src) {
    uint32_t d = (uint32_t)__cvta_generic_to_shared(dst);
    asm volatile("cp.async.cg.shared.global [%0], [%1], 16;\n" :: "r"(d), "l"(src));
}
__device__ __forceinline__ void ffma2(ull& acc, ull a, ull b) {
    asm volatile("fma.rn.f32x2 %0, %1, %2, %0;\n" : "+l"(acc) : "l"(a), "l"(b));
}

// ---------------- 1) gather + layernorm (fp32 out) ----------------
__global__ void __launch_bounds__(256) ln_kernel(
    const float* __restrict__ features,
    const float* __restrict__ ln_scale,
    const float* __restrict__ ln_bias)
{
    int l = blockIdx.x % 7;
    int m = blockIdx.x / 7;
    int layer = 24 - 4 * l;
    const float4* x = reinterpret_cast<const float4*>(
        features + ((size_t)m * NLF + layer) * DIM);
    int t = threadIdx.x;

    float4 a = x[t];
    float4 b = x[t + 256];
    float s  = a.x + a.y + a.z + a.w + b.x + b.y + b.z + b.w;
    float ss = a.x*a.x + a.y*a.y + a.z*a.z + a.w*a.w
             + b.x*b.x + b.y*b.y + b.z*b.z + b.w*b.w;

    __shared__ float shs[8], shss[8];
    float ws  = warp_sum(s);
    float wss = warp_sum(ss);
    int w = t >> 5, lane = t & 31;
    if (lane == 0) { shs[w] = ws; shss[w] = wss; }
    __syncthreads();
    float tot = 0.f, tot2 = 0.f;
#pragma unroll
    for (int i = 0; i < 8; i++) { tot += shs[i]; tot2 += shss[i]; }

    float mu  = tot * (1.0f / DIM);
    float var = tot2 * (1.0f / DIM) - mu * mu;
    float rs  = rsqrtf(var + LN_EPSF);

    const float4* sc = reinterpret_cast<const float4*>(ln_scale + (size_t)l * DIM);
    const float4* bi = reinterpret_cast<const float4*>(ln_bias  + (size_t)l * DIM);
    float4* o = reinterpret_cast<float4*>(g_xn + ((size_t)l * MTOT + m) * DIM);

    float4 s0 = sc[t],       b0 = bi[t];
    float4 s1 = sc[t + 256], b1 = bi[t + 256];
    float4 o0, o1;
    o0.x = (a.x - mu) * rs * s0.x + b0.x;
    o0.y = (a.y - mu) * rs * s0.y + b0.y;
    o0.z = (a.z - mu) * rs * s0.z + b0.z;
    o0.w = (a.w - mu) * rs * s0.w + b0.w;
    o1.x = (b.x - mu) * rs * s1.x + b1.x;
    o1.y = (b.y - mu) * rs * s1.y + b1.y;
    o1.z = (b.z - mu) * rs * s1.z + b1.z;
    o1.w = (b.w - mu) * rs * s1.w + b1.w;
    o[t] = o0;
    o[t + 256] = o1;
}

// ---------------- 2) FFMA2 GEMM v2: 128x128x16, 128 threads, 8Mx16N/thread ---
// A duplicated (v,v) pairs in smem with +4 float pad per 8 rows (conflict-free
// broadcast LDS.128). B natural layout (pairs along N), cp.async loaded.
// MODE 0: z<7: g_xn[z] @ w_norm[z]; z==7: features[:,:,24] @ w_in + b_in -> g_v slot z
// MODE 1: g_fuse @ w_out + vin + b_out -> g_vf
#define AROWF 320                 // padded A row: 128 dup pairs (256) + 16*4 pad
#define ABUF  (16 * AROWF)        // 5120 floats per stage
#define BBUF  (16 * 128)          // 2048 floats per stage
#define GSMEM ((2 * ABUF + 2 * BBUF) * 4)   // 57344 bytes

template<int NKT, int MODE>
__global__ void __launch_bounds__(128, 2) gemm_v2(
    const float* __restrict__ features,
    const float* __restrict__ w_norm,
    const float* __restrict__ w_x,      // w_in (MODE0) / w_out (MODE1)
    const float* __restrict__ bias)     // b_in (MODE0) / b_out (MODE1)
{
    extern __shared__ float sm[];
    float* As2 = sm;                    // [2][16][AROWF]
    float* Bs  = sm + 2 * ABUF;         // [2][16][128]

    int tid = threadIdx.x;
    int m0 = blockIdx.y * 128, n0 = blockIdx.x * 128;
    int z = (MODE == 0) ? blockIdx.z : 0;

    const float* A;
    const float* B;
    size_t lda;
    if (MODE == 0) {
        if (z < 7) {
            A = g_xn + (size_t)z * MTOT * DIM;
            lda = DIM;
            B = w_norm + (size_t)z * DIM * CTD;
        } else {
            A = features + (size_t)24 * DIM;
            lda = (size_t)NLF * DIM;
            B = w_x;
        }
    } else {
        A = g_fuse; lda = CTD; B = w_x;
    }

    // loader mapping
    int arow = tid;                                  // A: one row per thread, 16 k
    int brow = tid >> 3, bcol = (tid & 7) * 16;      // B: 16 k x 128 n
    const float* ag = A + (size_t)(m0 + arow) * lda;
    const float* bg = B + (size_t)brow * CTD + n0 + bcol;
    int aoff = 2 * arow + 4 * (arow >> 3);           // dup-pair offset within A row

    // compute mapping: ty in 0..15 (8 m-rows each), tx in 0..7 (16 n-cols each)
    int ty = tid >> 3, tx = tid & 7;

    ull acc[8][8];
#pragma unroll
    for (int i = 0; i < 8; i++)
#pragma unroll
        for (int j = 0; j < 8; j++) acc[i][j] = 0ull;

    float4 pa[4];

    // ---- prologue: tile 0 into buf 0 ----
#pragma unroll
    for (int j = 0; j < 4; j++)
        pa[j] = *reinterpret_cast<const float4*>(ag + j * 4);
#pragma unroll
    for (int j = 0; j < 4; j++)
        cp16(&Bs[brow * 128 + bcol + j * 4], bg + j * 4);
    asm volatile("cp.async.commit_group;\n" ::: "memory");
#pragma unroll
    for (int j = 0; j < 4; j++) {
        float vv[4] = {pa[j].x, pa[j].y, pa[j].z, pa[j].w};
#pragma unroll
        for (int e = 0; e < 4; e++) {
            int k = j * 4 + e;
            *reinterpret_cast<float2*>(&As2[k * AROWF + aoff]) =
                make_float2(vv[e], vv[e]);
        }
    }

    for (int kt = 0; kt < NKT; kt++) {
        int buf = kt & 1;
        asm volatile("cp.async.wait_group 0;\n" ::: "memory");
        __syncthreads();

        if (kt + 1 < NKT) {
            const float* an = ag + (kt + 1) * 16;
#pragma unroll
            for (int j = 0; j < 4; j++)
                pa[j] = *reinterpret_cast<const float4*>(an + j * 4);
            const float* bn = bg + (size_t)(kt + 1) * 16 * CTD;
            float* bd = Bs + (buf ^ 1) * BBUF;
#pragma unroll
            for (int j = 0; j < 4; j++)
                cp16(&bd[brow * 128 + bcol + j * 4], bn + j * 4);
            asm volatile("cp.async.commit_group;\n" ::: "memory");
        }

        const float* ab = As2 + buf * ABUF;
        const float* bb = Bs + buf * BBUF;
#pragma unroll
        for (int k = 0; k < 16; k++) {
            ull a[8], b[8];
#pragma unroll
            for (int j0 = 0; j0 < 4; j0++) {
                ulonglong2 t = *reinterpret_cast<const ulonglong2*>(
                    ab + k * AROWF + 20 * ty + 4 * j0);
                a[2 * j0] = t.x; a[2 * j0 + 1] = t.y;
            }
#pragma unroll
            for (int j1 = 0; j1 < 4; j1++) {
                ulonglong2 t = *reinterpret_cast<const ulonglong2*>(
                    bb + k * 128 + 32 * j1 + 4 * tx);
                b[2 * j1] = t.x; b[2 * j1 + 1] = t.y;
            }
#pragma unroll
            for (int i = 0; i < 8; i++)
#pragma unroll
                for (int j = 0; j < 8; j++) ffma2(acc[i][j], a[i], b[j]);
        }

        if (kt + 1 < NKT) {
            float* ad = As2 + (buf ^ 1) * ABUF;
#pragma unroll
            for (int j = 0; j < 4; j++) {
                float vv[4] = {pa[j].x, pa[j].y, pa[j].z, pa[j].w};
#pragma unroll
                for (int e = 0; e < 4; e++) {
                    int k = j * 4 + e;
                    *reinterpret_cast<float2*>(&ad[k * AROWF + aoff]) =
                        make_float2(vv[e], vv[e]);
                }
            }
        }
    }

    // ---- epilogue ----
#pragma unroll
    for (int i = 0; i < 8; i++) {
        int m = m0 + ty * 8 + i;
#pragma unroll
        for (int j1 = 0; j1 < 4; j1++) {
            int n = n0 + 32 * j1 + 4 * tx;
            float4 v;
            v.x = __uint_as_float((uint32_t)(acc[i][2 * j1] & 0xffffffffull));
            v.y = __uint_as_float((uint32_t)(acc[i][2 * j1] >> 32));
            v.z = __uint_as_float((uint32_t)(acc[i][2 * j1 + 1] & 0xffffffffull));
            v.w = __uint_as_float((uint32_t)(acc[i][2 * j1 + 1] >> 32));
            if (MODE == 0) {
                if (z == 7) {
                    float4 bb = *reinterpret_cast<const float4*>(bias + n);
                    v.x += bb.x; v.y += bb.y; v.z += bb.z; v.w += bb.w;
                }
                *reinterpret_cast<float4*>(
                    g_v + (size_t)m * (8 * CTD) + (size_t)z * CTD + n) = v;
            } else {
                float4 bb = *reinterpret_cast<const float4*>(bias + n);
                float4 vin = *reinterpret_cast<const float4*>(
                    g_v + (size_t)m * (8 * CTD) + 7 * CTD + n);
                v.x += bb.x + vin.x; v.y += bb.y + vin.y;
                v.z += bb.z + vin.z; v.w += bb.w + vin.w;
                *reinterpret_cast<float4*>(g_vf + (size_t)m * CTD + n) = v;
            }
        }
    }
}

// ---------------- 3) attention fuse ----------------
__global__ void __launch_bounds__(128) attn_kernel()
{
    int m = blockIdx.x, t = threadIdx.x;
    const float* vrow = g_v + (size_t)m * 8 * CTD;
    __shared__ float shp[6][4];
    __shared__ float slog[6];
    int w = t >> 5, lane = t & 31;

    for (int h = 0; h < HEADS; h++) {
        float q = vrow[h * HDIM + t] * ATT_SCALE;
        float kv[6];
#pragma unroll
        for (int l = 0; l < 6; l++)
            kv[l] = vrow[(size_t)(l + 1) * CTD + h * HDIM + t];
#pragma unroll
        for (int l = 0; l < 6; l++) {
            float p = warp_sum(q * kv[l]);
            if (lane == 0) shp[l][w] = p;
        }
        __syncthreads();
        if (t < 6) slog[t] = shp[t][0] + shp[t][1] + shp[t][2] + shp[t][3];
        __syncthreads();
        float mx = -1e30f;
#pragma unroll
        for (int l = 0; l < 6; l++) mx = fmaxf(mx, slog[l]);
        float e[6], sum = 0.f;
#pragma unroll
        for (int l = 0; l < 6; l++) { e[l] = expf(slog[l] - mx); sum += e[l]; }
        float inv = 1.0f / sum;
        float f = 0.f;
#pragma unroll
        for (int l = 0; l < 6; l++) f += (e[l] * inv) * kv[l];
        g_fuse[(size_t)m * CTD + h * HDIM + t] = f;
        __syncthreads();
    }
}

// ---------------- 5) per-row cosine ----------------
__global__ void __launch_bounds__(256) cos_kernel(const float* __restrict__ teacher)
{
    int m = blockIdx.x, t = threadIdx.x;
    const float4* a = reinterpret_cast<const float4*>(g_vf + (size_t)m * CTD);
    const float4* b = reinterpret_cast<const float4*>(teacher + (size_t)m * CTD);
    float4 x = a[t], y = b[t];
    float dot = x.x*y.x + x.y*y.y + x.z*y.z + x.w*y.w;
    float n1  = x.x*x.x + x.y*x.y + x.z*x.z + x.w*x.w;
    float n2  = y.x*y.x + y.y*y.y + y.z*y.z + y.w*y.w;

    __shared__ float sd[8], s1[8], s2[8];
    float wd = warp_sum(dot), w1 = warp_sum(n1), w2 = warp_sum(n2);
    int w = t >> 5, lane = t & 31;
    if (lane == 0) { sd[w] = wd; s1[w] = w1; s2[w] = w2; }
    __syncthreads();
    if (t == 0) {
        float td = 0.f, t1 = 0.f, t2 = 0.f;
#pragma unroll
        for (int i = 0; i < 8; i++) { td += sd[i]; t1 += s1[i]; t2 += s2[i]; }
        float na = fmaxf(sqrtf(t1), COS_EPSF);
        float nb = fmaxf(sqrtf(t2), COS_EPSF);
        g_cos[m] = td / (na * nb);
    }
}

// ---------------- 6) final deterministic reduction ----------------
__global__ void __launch_bounds__(512) final_kernel(float* __restrict__ out)
{
    __shared__ float sh[512];
    int t = threadIdx.x;
    float s = 0.f;
    for (int i = t; i < MTOT; i += 512) s += g_cos[i];
    sh[t] = s;
    __syncthreads();
    for (int o = 256; o > 0; o >>= 1) {
        if (t < o) sh[t] += sh[t + o];
        __syncthreads();
    }
    if (t == 0) out[0] = 1.0f - sh[0] / (float)MTOT;
}

// ---------------- launch ----------------
extern "C" void kernel_launch(void* const* d_in, const int* in_sizes, int n_in,
                              void* d_out, int out_size)
{
    const float* features = (const float*)d_in[0];
    const float* teacher  = (const float*)d_in[1];
    const float* ln_scale = (const float*)d_in[2];
    const float* ln_bias  = (const float*)d_in[3];
    const float* w_norm   = (const float*)d_in[4];
    const float* w_in     = (const float*)d_in[5];
    const float* b_in     = (const float*)d_in[6];
    const float* w_out    = (const float*)d_in[7];
    const float* b_out    = (const float*)d_in[8];
    float* out = (float*)d_out;

    cudaFuncSetAttribute(gemm_v2<DIM / 16, 0>,
                         cudaFuncAttributeMaxDynamicSharedMemorySize, GSMEM);
    cudaFuncSetAttribute(gemm_v2<CTD / 16, 1>,
                         cudaFuncAttributeMaxDynamicSharedMemorySize, GSMEM);

    ln_kernel<<<MTOT * 7, 256>>>(features, ln_scale, ln_bias);
    gemm_v2<DIM / 16, 0><<<dim3(CTD / 128, MTOT / 128, 8), 128, GSMEM>>>(
        features, w_norm, w_in, b_in);
    attn_kernel<<<MTOT, 128>>>();
    gemm_v2<CTD / 16, 1><<<dim3(CTD / 128, MTOT / 128, 1), 128, GSMEM>>>(
        features, nullptr, w_out, b_out);
    cos_kernel<<<MTOT, 256>>>(teacher);
    final_kernel<<<1, 512>>>(out);
}

// round 6
// speedup vs baseline: 11.5395x; 1.2358x over previous
#include <cuda_runtime.h>
#include <cuda_fp16.h>
#include <math.h>
#include <stdint.h>

// ---------------- problem constants ----------------
#define BT      8
#define SEQ     576
#define MTOT    (BT * SEQ)        // 4608
#define NLF     25
#define DIM     2048              // D
#define CTD     1024              // CT
#define HEADS   8
#define HDIM    128
#define ATT_SCALE 0.03125f
#define LN_EPSF   1e-5f
#define COS_EPSF  1e-8f

// ---------------- device scratch ----------------
__device__ __half g_xn[(size_t)8 * MTOT * DIM];   // slots 0..6 LN'd layers, slot 7 raw layer 24
__device__ __half g_wh[(size_t)8 * DIM * CTD];    // slots 0..6 w_norm, slot 7 w_in (fp16)
__device__ __half g_woh[(size_t)CTD * CTD];       // w_out fp16
__device__ float  g_v[(size_t)MTOT * 8 * CTD];    // per row: slots 0..6 vout, slot 7 vin
__device__ __half g_fuse[(size_t)MTOT * CTD];
__device__ float  g_vf[(size_t)MTOT * CTD];
__device__ float  g_cos[MTOT];

// ---------------- helpers ----------------
__device__ __forceinline__ float warp_sum(float v) {
#pragma unroll
    for (int o = 16; o > 0; o >>= 1) v += __shfl_xor_sync(0xffffffffu, v, o);
    return v;
}
__device__ __forceinline__ void cp16(void* dst, const void* src) {
    uint32_t d = (uint32_t)__cvta_generic_to_shared(dst);
    asm volatile("cp.async.cg.shared.global [%0], [%1], 16;\n" :: "r"(d), "l"(src));
}
// 4 floats -> 4 halves packed in uint2
__device__ __forceinline__ uint2 f4_to_h4(float4 v) {
    __half2 lo = __floats2half2_rn(v.x, v.y);
    __half2 hi = __floats2half2_rn(v.z, v.w);
    uint2 r;
    r.x = *reinterpret_cast<uint32_t*>(&lo);
    r.y = *reinterpret_cast<uint32_t*>(&hi);
    return r;
}

// ---------------- 0) convert weights to fp16 ----------------
#define WN4 ((size_t)7 * DIM * CTD / 4)
#define WI4 ((size_t)DIM * CTD / 4)
#define WO4 ((size_t)CTD * CTD / 4)
__global__ void __launch_bounds__(256) convert_weights(
    const float* __restrict__ wn, const float* __restrict__ wi,
    const float* __restrict__ wo)
{
    size_t i = (size_t)blockIdx.x * 256 + threadIdx.x;
    if (i < WN4) {
        reinterpret_cast<uint2*>(g_wh)[i] =
            f4_to_h4(reinterpret_cast<const float4*>(wn)[i]);
    } else if (i < WN4 + WI4) {
        size_t j = i - WN4;
        reinterpret_cast<uint2*>(g_wh + (size_t)7 * DIM * CTD)[j] =
            f4_to_h4(reinterpret_cast<const float4*>(wi)[j]);
    } else if (i < WN4 + WI4 + WO4) {
        size_t j = i - WN4 - WI4;
        reinterpret_cast<uint2*>(g_woh)[j] =
            f4_to_h4(reinterpret_cast<const float4*>(wo)[j]);
    }
}

// ---------------- 1) gather + layernorm -> fp16 ----------------
// grid MTOT*8: l<7 LN of layer 24-4l, l==7 raw copy of layer 24.
__global__ void __launch_bounds__(256) ln_kernel(
    const float* __restrict__ features,
    const float* __restrict__ ln_scale,
    const float* __restrict__ ln_bias)
{
    int l = blockIdx.x & 7;
    int m = blockIdx.x >> 3;
    int layer = (l < 7) ? (24 - 4 * l) : 24;
    const float4* x = reinterpret_cast<const float4*>(
        features + ((size_t)m * NLF + layer) * DIM);
    int t = threadIdx.x;

    float4 a = x[t];
    float4 b = x[t + 256];
    uint2* o = reinterpret_cast<uint2*>(g_xn + ((size_t)l * MTOT + m) * DIM);

    if (l == 7) {
        o[t] = f4_to_h4(a);
        o[t + 256] = f4_to_h4(b);
        return;
    }

    float s  = a.x + a.y + a.z + a.w + b.x + b.y + b.z + b.w;
    float ss = a.x*a.x + a.y*a.y + a.z*a.z + a.w*a.w
             + b.x*b.x + b.y*b.y + b.z*b.z + b.w*b.w;

    __shared__ float shs[8], shss[8];
    float ws  = warp_sum(s);
    float wss = warp_sum(ss);
    int w = t >> 5, lane = t & 31;
    if (lane == 0) { shs[w] = ws; shss[w] = wss; }
    __syncthreads();
    float tot = 0.f, tot2 = 0.f;
#pragma unroll
    for (int i = 0; i < 8; i++) { tot += shs[i]; tot2 += shss[i]; }

    float mu  = tot * (1.0f / DIM);
    float var = tot2 * (1.0f / DIM) - mu * mu;
    float rs  = rsqrtf(var + LN_EPSF);

    const float4* sc = reinterpret_cast<const float4*>(ln_scale + (size_t)l * DIM);
    const float4* bi = reinterpret_cast<const float4*>(ln_bias  + (size_t)l * DIM);
    float4 s0 = sc[t],       b0 = bi[t];
    float4 s1 = sc[t + 256], b1 = bi[t + 256];
    float4 o0, o1;
    o0.x = (a.x - mu) * rs * s0.x + b0.x;
    o0.y = (a.y - mu) * rs * s0.y + b0.y;
    o0.z = (a.z - mu) * rs * s0.z + b0.z;
    o0.w = (a.w - mu) * rs * s0.w + b0.w;
    o1.x = (b.x - mu) * rs * s1.x + b1.x;
    o1.y = (b.y - mu) * rs * s1.y + b1.y;
    o1.z = (b.z - mu) * rs * s1.z + b1.z;
    o1.w = (b.w - mu) * rs * s1.w + b1.w;
    o[t] = f4_to_h4(o0);
    o[t + 256] = f4_to_h4(o1);
}

// ---------------- 2) HFMA2 GEMM: 128x128x16 tile, 256 thr, 8Mx8N/thread -----
// A fp16 [M,K], dup (v,v) half2 pairs in smem; B fp16 [K,N] natural.
// half2 accumulators flushed to fp32 every 4 K-tiles (K=64).
// MODE 0: g_xn[z] @ g_wh[z] (+ b_in if z==7) -> g_v slot z
// MODE 1: g_fuse @ g_woh + vin + b_out -> g_vf
template<int NKT, int MODE>
__global__ void __launch_bounds__(256, 1) gemm_h(
    const float* __restrict__ bias)
{
    __shared__ __align__(16) __half2 As2[2][16][136];  // 17408 B, 8 h2 pad/row
    __shared__ __align__(16) __half  Bs[2][16][128];   // 8192 B

    int tid = threadIdx.x;
    int m0 = blockIdx.y * 128, n0 = blockIdx.x * 128;
    int z = (MODE == 0) ? blockIdx.z : 0;

    const __half* A;
    const __half* B;
    if (MODE == 0) {
        A = g_xn + (size_t)z * MTOT * DIM;
        B = g_wh + (size_t)z * DIM * CTD;
    } else {
        A = g_fuse;
        B = g_woh;
    }
    const int lda = (MODE == 0) ? DIM : CTD;

    // loader mapping
    int arow = tid >> 1, acol = (tid & 1) * 8;       // A: 128 rows x 16 halves
    int brow = tid >> 4, bcol = (tid & 15) * 8;      // B: 16 k-rows x 128 halves
    const __half* ag = A + (size_t)(m0 + arow) * lda + acol;
    const __half* bg = B + (size_t)brow * CTD + n0 + bcol;

    // compute mapping: ty 0..15 (8 m-rows), tx 0..15 (8 n-cols)
    int ty = tid >> 4, tx = tid & 15;

    float2  accf[8][4];
    __half2 acch[8][4];
#pragma unroll
    for (int i = 0; i < 8; i++)
#pragma unroll
        for (int j = 0; j < 4; j++) {
            accf[i][j] = make_float2(0.f, 0.f);
            acch[i][j] = __half2half2(__ushort_as_half(0));
        }

    uint4 pa;

    auto store_a = [&](int buf, uint4 raw) {
        const __half2* hp = reinterpret_cast<const __half2*>(&raw);
#pragma unroll
        for (int jj = 0; jj < 4; jj++) {
            __half lo = __low2half(hp[jj]), hi = __high2half(hp[jj]);
            As2[buf][acol + 2 * jj][arow]     = __half2half2(lo);
            As2[buf][acol + 2 * jj + 1][arow] = __half2half2(hi);
        }
    };

    // ---- prologue: tile 0 into buf 0 ----
    pa = *reinterpret_cast<const uint4*>(ag);
    cp16(&Bs[0][brow][bcol], bg);
    asm volatile("cp.async.commit_group;\n" ::: "memory");
    store_a(0, pa);

    for (int kt = 0; kt < NKT; kt++) {
        int buf = kt & 1;
        asm volatile("cp.async.wait_group 0;\n" ::: "memory");
        __syncthreads();

        if (kt + 1 < NKT) {
            pa = *reinterpret_cast<const uint4*>(ag + (kt + 1) * 16);
            cp16(&Bs[buf ^ 1][brow][bcol], bg + (size_t)(kt + 1) * 16 * CTD);
            asm volatile("cp.async.commit_group;\n" ::: "memory");
        }

#pragma unroll
        for (int k = 0; k < 16; k++) {
            __half2 a2[8], b2[4];
            *reinterpret_cast<uint4*>(&a2[0]) =
                *reinterpret_cast<const uint4*>(&As2[buf][k][ty * 8]);
            *reinterpret_cast<uint4*>(&a2[4]) =
                *reinterpret_cast<const uint4*>(&As2[buf][k][ty * 8 + 4]);
            *reinterpret_cast<uint4*>(&b2[0]) =
                *reinterpret_cast<const uint4*>(&Bs[buf][k][tx * 8]);
#pragma unroll
            for (int i = 0; i < 8; i++)
#pragma unroll
                for (int j = 0; j < 4; j++)
                    acch[i][j] = __hfma2(a2[i], b2[j], acch[i][j]);
        }

        if (kt + 1 < NKT) store_a(buf ^ 1, pa);

        if ((kt & 3) == 3 || kt == NKT - 1) {
#pragma unroll
            for (int i = 0; i < 8; i++)
#pragma unroll
                for (int j = 0; j < 4; j++) {
                    float2 t = __half22float2(acch[i][j]);
                    accf[i][j].x += t.x;
                    accf[i][j].y += t.y;
                    acch[i][j] = __half2half2(__ushort_as_half(0));
                }
        }
    }

    // ---- epilogue ----
#pragma unroll
    for (int i = 0; i < 8; i++) {
        int m = m0 + ty * 8 + i;
        int n = n0 + tx * 8;
#pragma unroll
        for (int jj = 0; jj < 2; jj++) {
            float4 v;
            v.x = accf[i][2 * jj].x;     v.y = accf[i][2 * jj].y;
            v.z = accf[i][2 * jj + 1].x; v.w = accf[i][2 * jj + 1].y;
            int nn = n + jj * 4;
            if (MODE == 0) {
                if (z == 7) {
                    float4 bb = *reinterpret_cast<const float4*>(bias + nn);
                    v.x += bb.x; v.y += bb.y; v.z += bb.z; v.w += bb.w;
                }
                *reinterpret_cast<float4*>(
                    g_v + (size_t)m * (8 * CTD) + (size_t)z * CTD + nn) = v;
            } else {
                float4 bb = *reinterpret_cast<const float4*>(bias + nn);
                float4 vin = *reinterpret_cast<const float4*>(
                    g_v + (size_t)m * (8 * CTD) + 7 * CTD + nn);
                v.x += bb.x + vin.x; v.y += bb.y + vin.y;
                v.z += bb.z + vin.z; v.w += bb.w + vin.w;
                *reinterpret_cast<float4*>(g_vf + (size_t)m * CTD + nn) = v;
            }
        }
    }
}

// ---------------- 3) attention fuse (fp32 in, fp16 out) ----------------
__global__ void __launch_bounds__(128) attn_kernel()
{
    int m = blockIdx.x, t = threadIdx.x;
    const float* vrow = g_v + (size_t)m * 8 * CTD;
    __shared__ float shp[6][4];
    __shared__ float slog[6];
    int w = t >> 5, lane = t & 31;

    for (int h = 0; h < HEADS; h++) {
        float q = vrow[h * HDIM + t] * ATT_SCALE;
        float kv[6];
#pragma unroll
        for (int l = 0; l < 6; l++)
            kv[l] = vrow[(size_t)(l + 1) * CTD + h * HDIM + t];
#pragma unroll
        for (int l = 0; l < 6; l++) {
            float p = warp_sum(q * kv[l]);
            if (lane == 0) shp[l][w] = p;
        }
        __syncthreads();
        if (t < 6) slog[t] = shp[t][0] + shp[t][1] + shp[t][2] + shp[t][3];
        __syncthreads();
        float mx = -1e30f;
#pragma unroll
        for (int l = 0; l < 6; l++) mx = fmaxf(mx, slog[l]);
        float e[6], sum = 0.f;
#pragma unroll
        for (int l = 0; l < 6; l++) { e[l] = expf(slog[l] - mx); sum += e[l]; }
        float inv = 1.0f / sum;
        float f = 0.f;
#pragma unroll
        for (int l = 0; l < 6; l++) f += (e[l] * inv) * kv[l];
        g_fuse[(size_t)m * CTD + h * HDIM + t] = __float2half_rn(f);
        __syncthreads();
    }
}

// ---------------- 5) per-row cosine ----------------
__global__ void __launch_bounds__(256) cos_kernel(const float* __restrict__ teacher)
{
    int m = blockIdx.x, t = threadIdx.x;
    const float4* a = reinterpret_cast<const float4*>(g_vf + (size_t)m * CTD);
    const float4* b = reinterpret_cast<const float4*>(teacher + (size_t)m * CTD);
    float4 x = a[t], y = b[t];
    float dot = x.x*y.x + x.y*y.y + x.z*y.z + x.w*y.w;
    float n1  = x.x*x.x + x.y*x.y + x.z*x.z + x.w*x.w;
    float n2  = y.x*y.x + y.y*y.y + y.z*y.z + y.w*y.w;

    __shared__ float sd[8], s1[8], s2[8];
    float wd = warp_sum(dot), w1 = warp_sum(n1), w2 = warp_sum(n2);
    int w = t >> 5, lane = t & 31;
    if (lane == 0) { sd[w] = wd; s1[w] = w1; s2[w] = w2; }
    __syncthreads();
    if (t == 0) {
        float td = 0.f, t1 = 0.f, t2 = 0.f;
#pragma unroll
        for (int i = 0; i < 8; i++) { td += sd[i]; t1 += s1[i]; t2 += s2[i]; }
        float na = fmaxf(sqrtf(t1), COS_EPSF);
        float nb = fmaxf(sqrtf(t2), COS_EPSF);
        g_cos[m] = td / (na * nb);
    }
}

// ---------------- 6) final deterministic reduction ----------------
__global__ void __launch_bounds__(512) final_kernel(float* __restrict__ out)
{
    __shared__ float sh[512];
    int t = threadIdx.x;
    float s = 0.f;
    for (int i = t; i < MTOT; i += 512) s += g_cos[i];
    sh[t] = s;
    __syncthreads();
    for (int o = 256; o > 0; o >>= 1) {
        if (t < o) sh[t] += sh[t + o];
        __syncthreads();
    }
    if (t == 0) out[0] = 1.0f - sh[0] / (float)MTOT;
}

// ---------------- launch ----------------
extern "C" void kernel_launch(void* const* d_in, const int* in_sizes, int n_in,
                              void* d_out, int out_size)
{
    const float* features = (const float*)d_in[0];
    const float* teacher  = (const float*)d_in[1];
    const float* ln_scale = (const float*)d_in[2];
    const float* ln_bias  = (const float*)d_in[3];
    const float* w_norm   = (const float*)d_in[4];
    const float* w_in     = (const float*)d_in[5];
    const float* b_in     = (const float*)d_in[6];
    const float* w_out    = (const float*)d_in[7];
    const float* b_out    = (const float*)d_in[8];
    float* out = (float*)d_out;

    size_t total4 = WN4 + WI4 + WO4;
    convert_weights<<<(unsigned)((total4 + 255) / 256), 256>>>(w_norm, w_in, w_out);
    ln_kernel<<<MTOT * 8, 256>>>(features, ln_scale, ln_bias);
    gemm_h<DIM / 16, 0><<<dim3(CTD / 128, MTOT / 128, 8), 256>>>(b_in);
    attn_kernel<<<MTOT, 128>>>();
    gemm_h<CTD / 16, 1><<<dim3(CTD / 128, MTOT / 128, 1), 256>>>(b_out);
    cos_kernel<<<MTOT, 256>>>(teacher);
    final_kernel<<<1, 512>>>(out);
}

// round 7
// speedup vs baseline: 12.0424x; 1.0436x over previous
#include <cuda_runtime.h>
#include <cuda_fp16.h>
#include <math.h>
#include <stdint.h>

// ---------------- problem constants ----------------
#define BT      8
#define SEQ     576
#define MTOT    (BT * SEQ)        // 4608
#define NLF     25
#define DIM     2048              // D
#define CTD     1024              // CT
#define HEADS   8
#define HDIM    128
#define ATT_SCALE 0.03125f
#define LN_EPSF   1e-5f
#define COS_EPSF  1e-8f

// ---------------- device scratch ----------------
__device__ __half g_xn[(size_t)8 * MTOT * DIM];   // slots 0..6 LN'd layers, slot 7 raw layer 24
__device__ __half g_wh[(size_t)8 * DIM * CTD];    // slots 0..6 w_norm, slot 7 w_in (fp16)
__device__ __half g_woh[(size_t)CTD * CTD];       // w_out fp16
__device__ float  g_v[(size_t)MTOT * 8 * CTD];    // per row: slots 0..6 vout, slot 7 vin
__device__ __half g_fuse[(size_t)MTOT * CTD];
__device__ float  g_vf[(size_t)MTOT * CTD];
__device__ float  g_cos[MTOT];

// ---------------- helpers ----------------
__device__ __forceinline__ float warp_sum(float v) {
#pragma unroll
    for (int o = 16; o > 0; o >>= 1) v += __shfl_xor_sync(0xffffffffu, v, o);
    return v;
}
__device__ __forceinline__ void cp16(void* dst, const void* src) {
    uint32_t d = (uint32_t)__cvta_generic_to_shared(dst);
    asm volatile("cp.async.cg.shared.global [%0], [%1], 16;\n" :: "r"(d), "l"(src));
}
__device__ __forceinline__ uint2 f4_to_h4(float4 v) {
    __half2 lo = __floats2half2_rn(v.x, v.y);
    __half2 hi = __floats2half2_rn(v.z, v.w);
    uint2 r;
    r.x = *reinterpret_cast<uint32_t*>(&lo);
    r.y = *reinterpret_cast<uint32_t*>(&hi);
    return r;
}

// ---------------- 0) convert weights to fp16 ----------------
#define WN4 ((size_t)7 * DIM * CTD / 4)
#define WI4 ((size_t)DIM * CTD / 4)
#define WO4 ((size_t)CTD * CTD / 4)
__global__ void __launch_bounds__(256) convert_weights(
    const float* __restrict__ wn, const float* __restrict__ wi,
    const float* __restrict__ wo)
{
    size_t i = (size_t)blockIdx.x * 256 + threadIdx.x;
    if (i < WN4) {
        reinterpret_cast<uint2*>(g_wh)[i] =
            f4_to_h4(reinterpret_cast<const float4*>(wn)[i]);
    } else if (i < WN4 + WI4) {
        size_t j = i - WN4;
        reinterpret_cast<uint2*>(g_wh + (size_t)7 * DIM * CTD)[j] =
            f4_to_h4(reinterpret_cast<const float4*>(wi)[j]);
    } else if (i < WN4 + WI4 + WO4) {
        size_t j = i - WN4 - WI4;
        reinterpret_cast<uint2*>(g_woh)[j] =
            f4_to_h4(reinterpret_cast<const float4*>(wo)[j]);
    }
}

// ---------------- 1) gather + layernorm -> fp16 ----------------
__global__ void __launch_bounds__(256) ln_kernel(
    const float* __restrict__ features,
    const float* __restrict__ ln_scale,
    const float* __restrict__ ln_bias)
{
    int l = blockIdx.x & 7;
    int m = blockIdx.x >> 3;
    int layer = (l < 7) ? (24 - 4 * l) : 24;
    const float4* x = reinterpret_cast<const float4*>(
        features + ((size_t)m * NLF + layer) * DIM);
    int t = threadIdx.x;

    float4 a = x[t];
    float4 b = x[t + 256];
    uint2* o = reinterpret_cast<uint2*>(g_xn + ((size_t)l * MTOT + m) * DIM);

    if (l == 7) {
        o[t] = f4_to_h4(a);
        o[t + 256] = f4_to_h4(b);
        return;
    }

    float s  = a.x + a.y + a.z + a.w + b.x + b.y + b.z + b.w;
    float ss = a.x*a.x + a.y*a.y + a.z*a.z + a.w*a.w
             + b.x*b.x + b.y*b.y + b.z*b.z + b.w*b.w;

    __shared__ float shs[8], shss[8];
    float ws  = warp_sum(s);
    float wss = warp_sum(ss);
    int w = t >> 5, lane = t & 31;
    if (lane == 0) { shs[w] = ws; shss[w] = wss; }
    __syncthreads();
    float tot = 0.f, tot2 = 0.f;
#pragma unroll
    for (int i = 0; i < 8; i++) { tot += shs[i]; tot2 += shss[i]; }

    float mu  = tot * (1.0f / DIM);
    float var = tot2 * (1.0f / DIM) - mu * mu;
    float rs  = rsqrtf(var + LN_EPSF);

    const float4* sc = reinterpret_cast<const float4*>(ln_scale + (size_t)l * DIM);
    const float4* bi = reinterpret_cast<const float4*>(ln_bias  + (size_t)l * DIM);
    float4 s0 = sc[t],       b0 = bi[t];
    float4 s1 = sc[t + 256], b1 = bi[t + 256];
    float4 o0, o1;
    o0.x = (a.x - mu) * rs * s0.x + b0.x;
    o0.y = (a.y - mu) * rs * s0.y + b0.y;
    o0.z = (a.z - mu) * rs * s0.z + b0.z;
    o0.w = (a.w - mu) * rs * s0.w + b0.w;
    o1.x = (b.x - mu) * rs * s1.x + b1.x;
    o1.y = (b.y - mu) * rs * s1.y + b1.y;
    o1.z = (b.z - mu) * rs * s1.z + b1.z;
    o1.w = (b.w - mu) * rs * s1.w + b1.w;
    o[t] = f4_to_h4(o0);
    o[t + 256] = f4_to_h4(o1);
}

// ---------------- 2) HFMA2 GEMM v2: 128x128x16 tile, 128 thr, 8Mx16N/thread -
// 2 CTAs/SM. A dup (v,v) half2 pairs in smem; B fp16 [K,N] natural via cp.async.
// half2 accumulators flushed to fp32 regs every 4 K-tiles (K=64).
// MODE 0: g_xn[z] @ g_wh[z] (+ b_in if z==7) -> g_v slot z
// MODE 1: g_fuse @ g_woh + vin + b_out -> g_vf
template<int NKT, int MODE>
__global__ void __launch_bounds__(128, 2) gemm_h2(
    const float* __restrict__ bias)
{
    __shared__ __align__(16) uint32_t As2[2][16][128];  // dup half2 pairs, 16 KB
    __shared__ __align__(16) __half   Bs[2][16][128];   // 8 KB

    int tid = threadIdx.x;
    int m0 = blockIdx.y * 128, n0 = blockIdx.x * 128;
    int z = (MODE == 0) ? blockIdx.z : 0;

    const __half* A;
    const __half* B;
    if (MODE == 0) {
        A = g_xn + (size_t)z * MTOT * DIM;
        B = g_wh + (size_t)z * DIM * CTD;
    } else {
        A = g_fuse;
        B = g_woh;
    }
    const int lda = (MODE == 0) ? DIM : CTD;

    // A loader: one M-row per thread, 16 halves (2 uint4) per tile
    const __half* ag = A + (size_t)(m0 + tid) * lda;
    // B loader: 2 units of 16B per thread; unit -> (krow, col16)
    int bu = tid * 2;
    int br0 = bu >> 4,      bc0 = (bu & 15) * 8;
    int br1 = (bu + 1) >> 4, bc1 = ((bu + 1) & 15) * 8;
    const __half* bg0 = B + (size_t)br0 * CTD + n0 + bc0;
    const __half* bg1 = B + (size_t)br1 * CTD + n0 + bc1;

    // compute mapping: ty 0..15 (8 m-rows), tx 0..7 (16 n-cols)
    int ty = tid >> 3, tx = tid & 7;

    float2  accf[8][8];
    __half2 acch[8][8];
#pragma unroll
    for (int i = 0; i < 8; i++)
#pragma unroll
        for (int j = 0; j < 8; j++) {
            accf[i][j] = make_float2(0.f, 0.f);
            acch[i][j] = __half2half2(__ushort_as_half(0));
        }

    uint4 pa0, pa1;

    auto store_a = [&](int buf, uint4 r0, uint4 r1) {
        const __half2* h0 = reinterpret_cast<const __half2*>(&r0);
        const __half2* h1 = reinterpret_cast<const __half2*>(&r1);
#pragma unroll
        for (int jj = 0; jj < 4; jj++) {
            __half2 dlo = __half2half2(__low2half(h0[jj]));
            __half2 dhi = __half2half2(__high2half(h0[jj]));
            As2[buf][2 * jj][tid]     = *reinterpret_cast<uint32_t*>(&dlo);
            As2[buf][2 * jj + 1][tid] = *reinterpret_cast<uint32_t*>(&dhi);
        }
#pragma unroll
        for (int jj = 0; jj < 4; jj++) {
            __half2 dlo = __half2half2(__low2half(h1[jj]));
            __half2 dhi = __half2half2(__high2half(h1[jj]));
            As2[buf][8 + 2 * jj][tid]     = *reinterpret_cast<uint32_t*>(&dlo);
            As2[buf][8 + 2 * jj + 1][tid] = *reinterpret_cast<uint32_t*>(&dhi);
        }
    };

    // ---- prologue: tile 0 into buf 0 ----
    pa0 = *reinterpret_cast<const uint4*>(ag);
    pa1 = *reinterpret_cast<const uint4*>(ag + 8);
    cp16(&Bs[0][br0][bc0], bg0);
    cp16(&Bs[0][br1][bc1], bg1);
    asm volatile("cp.async.commit_group;\n" ::: "memory");
    store_a(0, pa0, pa1);

    for (int kt = 0; kt < NKT; kt++) {
        int buf = kt & 1;
        asm volatile("cp.async.wait_group 0;\n" ::: "memory");
        __syncthreads();

        if (kt + 1 < NKT) {
            pa0 = *reinterpret_cast<const uint4*>(ag + (kt + 1) * 16);
            pa1 = *reinterpret_cast<const uint4*>(ag + (kt + 1) * 16 + 8);
            cp16(&Bs[buf ^ 1][br0][bc0], bg0 + (size_t)(kt + 1) * 16 * CTD);
            cp16(&Bs[buf ^ 1][br1][bc1], bg1 + (size_t)(kt + 1) * 16 * CTD);
            asm volatile("cp.async.commit_group;\n" ::: "memory");
        }

#pragma unroll
        for (int k = 0; k < 16; k++) {
            __half2 a2[8], b2[8];
            *reinterpret_cast<uint4*>(&a2[0]) =
                *reinterpret_cast<const uint4*>(&As2[buf][k][ty * 8]);
            *reinterpret_cast<uint4*>(&a2[4]) =
                *reinterpret_cast<const uint4*>(&As2[buf][k][ty * 8 + 4]);
            *reinterpret_cast<uint4*>(&b2[0]) =
                *reinterpret_cast<const uint4*>(&Bs[buf][k][tx * 16]);
            *reinterpret_cast<uint4*>(&b2[4]) =
                *reinterpret_cast<const uint4*>(&Bs[buf][k][tx * 16 + 8]);
#pragma unroll
            for (int i = 0; i < 8; i++)
#pragma unroll
                for (int j = 0; j < 8; j++)
                    acch[i][j] = __hfma2(a2[i], b2[j], acch[i][j]);
        }

        if (kt + 1 < NKT) store_a(buf ^ 1, pa0, pa1);

        if ((kt & 3) == 3 || kt == NKT - 1) {
#pragma unroll
            for (int i = 0; i < 8; i++)
#pragma unroll
                for (int j = 0; j < 8; j++) {
                    float2 t = __half22float2(acch[i][j]);
                    accf[i][j].x += t.x;
                    accf[i][j].y += t.y;
                    acch[i][j] = __half2half2(__ushort_as_half(0));
                }
        }
    }

    // ---- epilogue ----
#pragma unroll
    for (int i = 0; i < 8; i++) {
        int m = m0 + ty * 8 + i;
        int nb = n0 + tx * 16;
#pragma unroll
        for (int jj = 0; jj < 4; jj++) {
            float4 v;
            v.x = accf[i][2 * jj].x;     v.y = accf[i][2 * jj].y;
            v.z = accf[i][2 * jj + 1].x; v.w = accf[i][2 * jj + 1].y;
            int nn = nb + jj * 4;
            if (MODE == 0) {
                if (z == 7) {
                    float4 bb = *reinterpret_cast<const float4*>(bias + nn);
                    v.x += bb.x; v.y += bb.y; v.z += bb.z; v.w += bb.w;
                }
                *reinterpret_cast<float4*>(
                    g_v + (size_t)m * (8 * CTD) + (size_t)z * CTD + nn) = v;
            } else {
                float4 bb = *reinterpret_cast<const float4*>(bias + nn);
                float4 vin = *reinterpret_cast<const float4*>(
                    g_v + (size_t)m * (8 * CTD) + 7 * CTD + nn);
                v.x += bb.x + vin.x; v.y += bb.y + vin.y;
                v.z += bb.z + vin.z; v.w += bb.w + vin.w;
                *reinterpret_cast<float4*>(g_vf + (size_t)m * CTD + nn) = v;
            }
        }
    }
}

// ---------------- 3) attention fuse (fp32 in, fp16 out) ----------------
__global__ void __launch_bounds__(128) attn_kernel()
{
    int m = blockIdx.x, t = threadIdx.x;
    const float* vrow = g_v + (size_t)m * 8 * CTD;
    __shared__ float shp[6][4];
    __shared__ float slog[6];
    int w = t >> 5, lane = t & 31;

    for (int h = 0; h < HEADS; h++) {
        float q = vrow[h * HDIM + t] * ATT_SCALE;
        float kv[6];
#pragma unroll
        for (int l = 0; l < 6; l++)
            kv[l] = vrow[(size_t)(l + 1) * CTD + h * HDIM + t];
#pragma unroll
        for (int l = 0; l < 6; l++) {
            float p = warp_sum(q * kv[l]);
            if (lane == 0) shp[l][w] = p;
        }
        __syncthreads();
        if (t < 6) slog[t] = shp[t][0] + shp[t][1] + shp[t][2] + shp[t][3];
        __syncthreads();
        float mx = -1e30f;
#pragma unroll
        for (int l = 0; l < 6; l++) mx = fmaxf(mx, slog[l]);
        float e[6], sum = 0.f;
#pragma unroll
        for (int l = 0; l < 6; l++) { e[l] = expf(slog[l] - mx); sum += e[l]; }
        float inv = 1.0f / sum;
        float f = 0.f;
#pragma unroll
        for (int l = 0; l < 6; l++) f += (e[l] * inv) * kv[l];
        g_fuse[(size_t)m * CTD + h * HDIM + t] = __float2half_rn(f);
        __syncthreads();
    }
}

// ---------------- 5) per-row cosine ----------------
__global__ void __launch_bounds__(256) cos_kernel(const float* __restrict__ teacher)
{
    int m = blockIdx.x, t = threadIdx.x;
    const float4* a = reinterpret_cast<const float4*>(g_vf + (size_t)m * CTD);
    const float4* b = reinterpret_cast<const float4*>(teacher + (size_t)m * CTD);
    float4 x = a[t], y = b[t];
    float dot = x.x*y.x + x.y*y.y + x.z*y.z + x.w*y.w;
    float n1  = x.x*x.x + x.y*x.y + x.z*x.z + x.w*x.w;
    float n2  = y.x*y.x + y.y*y.y + y.z*y.z + y.w*y.w;

    __shared__ float sd[8], s1[8], s2[8];
    float wd = warp_sum(dot), w1 = warp_sum(n1), w2 = warp_sum(n2);
    int w = t >> 5, lane = t & 31;
    if (lane == 0) { sd[w] = wd; s1[w] = w1; s2[w] = w2; }
    __syncthreads();
    if (t == 0) {
        float td = 0.f, t1 = 0.f, t2 = 0.f;
#pragma unroll
        for (int i = 0; i < 8; i++) { td += sd[i]; t1 += s1[i]; t2 += s2[i]; }
        float na = fmaxf(sqrtf(t1), COS_EPSF);
        float nb = fmaxf(sqrtf(t2), COS_EPSF);
        g_cos[m] = td / (na * nb);
    }
}

// ---------------- 6) final deterministic reduction ----------------
__global__ void __launch_bounds__(512) final_kernel(float* __restrict__ out)
{
    __shared__ float sh[512];
    int t = threadIdx.x;
    float s = 0.f;
    for (int i = t; i < MTOT; i += 512) s += g_cos[i];
    sh[t] = s;
    __syncthreads();
    for (int o = 256; o > 0; o >>= 1) {
        if (t < o) sh[t] += sh[t + o];
        __syncthreads();
    }
    if (t == 0) out[0] = 1.0f - sh[0] / (float)MTOT;
}

// ---------------- launch ----------------
extern "C" void kernel_launch(void* const* d_in, const int* in_sizes, int n_in,
                              void* d_out, int out_size)
{
    const float* features = (const float*)d_in[0];
    const float* teacher  = (const float*)d_in[1];
    const float* ln_scale = (const float*)d_in[2];
    const float* ln_bias  = (const float*)d_in[3];
    const float* w_norm   = (const float*)d_in[4];
    const float* w_in     = (const float*)d_in[5];
    const float* b_in     = (const float*)d_in[6];
    const float* w_out    = (const float*)d_in[7];
    const float* b_out    = (const float*)d_in[8];
    float* out = (float*)d_out;

    size_t total4 = WN4 + WI4 + WO4;
    convert_weights<<<(unsigned)((total4 + 255) / 256), 256>>>(w_norm, w_in, w_out);
    ln_kernel<<<MTOT * 8, 256>>>(features, ln_scale, ln_bias);
    gemm_h2<DIM / 16, 0><<<dim3(CTD / 128, MTOT / 128, 8), 128>>>(b_in);
    attn_kernel<<<MTOT, 128>>>();
    gemm_h2<CTD / 16, 1><<<dim3(CTD / 128, MTOT / 128, 1), 128>>>(b_out);
    cos_kernel<<<MTOT, 256>>>(teacher);
    final_kernel<<<1, 512>>>(out);
}